// round 2
// baseline (speedup 1.0000x reference)
#include <cuda_runtime.h>
#include <math.h>
#include <stdint.h>

// Problem dimensions (fixed by the dataset)
#define SEQ   2048
#define DIN   11008
#define DOUT  4096
#define KR    4096   // rotation dim (== DOUT)

// ---------------------------------------------------------------------------
// Scratch (no cudaMalloc allowed -> __device__ globals)
// ---------------------------------------------------------------------------
__device__ float g_W [(size_t)DOUT * DIN];   // W' = R^T (weight*S)   [o][i]
__device__ float g_WT[(size_t)DIN  * DOUT];  // quantized W, transposed [i][o]
__device__ float g_xT[(size_t)DIN  * SEQ];   // x transposed [i][s]
__device__ float g_wscale[DOUT];             // per-row weight quant scale
__device__ float g_bias  [DOUT];             // rotated bias

// ---------------------------------------------------------------------------
// Block reduce (max)
// ---------------------------------------------------------------------------
__device__ __forceinline__ float block_reduce_max(float v) {
    __shared__ float sh[32];
    int lane = threadIdx.x & 31;
    int wid  = threadIdx.x >> 5;
    #pragma unroll
    for (int o = 16; o; o >>= 1) v = fmaxf(v, __shfl_xor_sync(0xffffffffu, v, o));
    if (lane == 0) sh[wid] = v;
    __syncthreads();
    int nw = blockDim.x >> 5;
    v = (threadIdx.x < (unsigned)nw) ? sh[threadIdx.x] : 0.0f;
    if (wid == 0) {
        #pragma unroll
        for (int o = 16; o; o >>= 1) v = fmaxf(v, __shfl_xor_sync(0xffffffffu, v, o));
    }
    if (threadIdx.x == 0) sh[0] = v;
    __syncthreads();
    return sh[0];
}

// ---------------------------------------------------------------------------
// TN SGEMM: C[m][n] = sum_k A[k][m] * B[k][n]   (A,B are K-major)
// BM=BN=128, BK=8, 256 threads, 8x8 per-thread tile.
// Global->register prefetch of the next K-tile overlaps LDG latency with FFMA.
// Optional per-column scale (GEMM1) / per-column bias (GEMM2) epilogue.
// Assumes M%128==0, N%128==0, K%8==0 (true for all our shapes).
// ---------------------------------------------------------------------------
__global__ __launch_bounds__(256)
void sgemm_tn(const float* __restrict__ A, int lda,
              const float* __restrict__ B, int ldb,
              float* __restrict__ C, int ldc, int K,
              const float* __restrict__ colScale,
              const float* __restrict__ colBias)
{
    const int BM = 128, BN = 128, BK = 8;
    __shared__ float As[BK][BM];
    __shared__ float Bs[BK][BN];

    const int tid = threadIdx.x;
    const int bm  = blockIdx.y * BM;
    const int bn  = blockIdx.x * BN;

    // loader: 256 threads -> 8 rows x 32 float4 cols
    const int lr = tid >> 5;            // 0..7  (k within tile)
    const int lc = (tid & 31) << 2;     // 0..124 step 4

    const float* Aptr = A + (size_t)lr * lda + bm + lc;
    const float* Bptr = B + (size_t)lr * ldb + bn + lc;

    const int tx = tid & 15;            // n-dir
    const int ty = tid >> 4;            // m-dir

    float acc[8][8];
    #pragma unroll
    for (int i = 0; i < 8; i++)
        #pragma unroll
        for (int j = 0; j < 8; j++) acc[i][j] = 0.0f;

    float a[8], b[8];

    // preload first tile
    float4 aReg = *(const float4*)Aptr;
    float4 bReg = *(const float4*)Bptr;

    for (int k0 = 0; k0 < K; k0 += BK) {
        *(float4*)&As[lr][lc] = aReg;
        *(float4*)&Bs[lr][lc] = bReg;
        __syncthreads();

        // prefetch next tile (overlaps with the FFMA block below)
        Aptr += (size_t)BK * lda;
        Bptr += (size_t)BK * ldb;
        if (k0 + BK < K) {
            aReg = *(const float4*)Aptr;
            bReg = *(const float4*)Bptr;
        }

        #pragma unroll
        for (int kk = 0; kk < BK; kk++) {
            *(float4*)&a[0] = *(float4*)&As[kk][ty * 8];
            *(float4*)&a[4] = *(float4*)&As[kk][ty * 8 + 4];
            *(float4*)&b[0] = *(float4*)&Bs[kk][tx * 8];
            *(float4*)&b[4] = *(float4*)&Bs[kk][tx * 8 + 4];
            #pragma unroll
            for (int i = 0; i < 8; i++)
                #pragma unroll
                for (int j = 0; j < 8; j++)
                    acc[i][j] = fmaf(a[i], b[j], acc[i][j]);
        }
        __syncthreads();
    }

    // epilogue
    #pragma unroll
    for (int i = 0; i < 8; i++) {
        const int row = bm + ty * 8 + i;
        #pragma unroll
        for (int j = 0; j < 8; j += 4) {
            const int col = bn + tx * 8 + j;
            float4 v = make_float4(acc[i][j], acc[i][j+1], acc[i][j+2], acc[i][j+3]);
            if (colScale) {
                const float4 s = *(const float4*)&colScale[col];
                v.x *= s.x; v.y *= s.y; v.z *= s.z; v.w *= s.w;
            }
            if (colBias) {
                const float4 bb = *(const float4*)&colBias[col];
                v.x += bb.x; v.y += bb.y; v.z += bb.z; v.w += bb.w;
            }
            *(float4*)&C[(size_t)row * ldc + col] = v;
        }
    }
}

// ---------------------------------------------------------------------------
// Rotated bias: b'[o] = sum_k R[k][o] * bias[k]
// ---------------------------------------------------------------------------
__global__ void rot_bias_kernel(const float* __restrict__ R,
                                const float* __restrict__ bias,
                                float* __restrict__ out)
{
    const int o = blockIdx.x * blockDim.x + threadIdx.x;
    if (o >= DOUT) return;
    float acc = 0.0f;
    for (int k = 0; k < KR; k++)
        acc = fmaf(R[(size_t)k * DOUT + o], bias[k], acc);
    out[o] = acc;
}

// ---------------------------------------------------------------------------
// Per-row max(|W'|) -> quant scale   (one block per output row)
// ---------------------------------------------------------------------------
__global__ void wrowmax_kernel(const float* __restrict__ W,
                               float* __restrict__ scale)
{
    const int row = blockIdx.x;
    const float* p = W + (size_t)row * DIN;
    float m = 0.0f;
    for (int i = threadIdx.x; i < DIN; i += blockDim.x)
        m = fmaxf(m, fabsf(p[i]));
    m = block_reduce_max(m);
    if (threadIdx.x == 0)
        scale[row] = fmaxf(__fdiv_rn(m, 127.0f), 1e-8f);
}

// ---------------------------------------------------------------------------
// Fused 8-bit fake-quant + transpose: WT[i][o] = quant(W[o][i])
// 32x32 tiles, 32x8 threads.
// ---------------------------------------------------------------------------
__global__ void quant_transpose_kernel(const float* __restrict__ W,
                                       const float* __restrict__ scale,
                                       float* __restrict__ WT)
{
    __shared__ float t[32][33];
    const int i0 = blockIdx.x * 32;
    const int o0 = blockIdx.y * 32;
    const int x = threadIdx.x;
    #pragma unroll
    for (int r = threadIdx.y; r < 32; r += 8) {
        const int o = o0 + r;
        const float s = scale[o];
        const float v = W[(size_t)o * DIN + i0 + x];
        float q = rintf(__fdiv_rn(v, s));           // round-half-even, IEEE div
        q = fminf(fmaxf(q, -128.0f), 127.0f);
        t[r][x] = q * s;
    }
    __syncthreads();
    #pragma unroll
    for (int r = threadIdx.y; r < 32; r += 8) {
        WT[(size_t)(i0 + r) * DOUT + o0 + x] = t[x][r];
    }
}

// ---------------------------------------------------------------------------
// Plain 32x32 tiled transpose: dst[c][r] = src[r][c]  (rows x cols -> cols x rows)
// ---------------------------------------------------------------------------
__global__ void transpose_kernel(const float* __restrict__ src,
                                 float* __restrict__ dst,
                                 int rows, int cols)
{
    __shared__ float t[32][33];
    const int c0 = blockIdx.x * 32;
    const int r0 = blockIdx.y * 32;
    #pragma unroll
    for (int r = threadIdx.y; r < 32; r += 8)
        t[r][threadIdx.x] = src[(size_t)(r0 + r) * cols + c0 + threadIdx.x];
    __syncthreads();
    #pragma unroll
    for (int c = threadIdx.y; c < 32; c += 8)
        dst[(size_t)(c0 + c) * rows + r0 + threadIdx.x] = t[threadIdx.x][c];
}

// ---------------------------------------------------------------------------
// 16-bit per-token fake-quant, in place. One block per token row.
// ---------------------------------------------------------------------------
__global__ void out_quant_kernel(float* __restrict__ out)
{
    const int s = blockIdx.x;
    float* p = out + (size_t)s * DOUT;
    float m = 0.0f;
    for (int i = threadIdx.x; i < DOUT; i += blockDim.x)
        m = fmaxf(m, fabsf(p[i]));
    m = block_reduce_max(m);
    const float sc = fmaxf(__fdiv_rn(m, 32767.0f), 1e-8f);
    for (int i = threadIdx.x; i < DOUT; i += blockDim.x) {
        float q = rintf(__fdiv_rn(p[i], sc));
        q = fminf(fmaxf(q, -32768.0f), 32767.0f);
        p[i] = q * sc;
    }
}

// ---------------------------------------------------------------------------
// Launch
// ---------------------------------------------------------------------------
extern "C" void kernel_launch(void* const* d_in, const int* in_sizes, int n_in,
                              void* d_out, int out_size)
{
    const float* d_x    = (const float*)d_in[0];  // [1, 2048, 11008]
    const float* d_w    = (const float*)d_in[1];  // [4096, 11008]
    const float* d_b    = (const float*)d_in[2];  // [4096]
    const float* d_S    = (const float*)d_in[3];  // [11008]
    const float* d_R    = (const float*)d_in[4];  // [4096, 4096]
    float*       d_outp = (float*)d_out;          // [2048, 4096]

    float* gW, *gWT, *gxT, *gws, *gbias;
    cudaGetSymbolAddress((void**)&gW,    g_W);
    cudaGetSymbolAddress((void**)&gWT,   g_WT);
    cudaGetSymbolAddress((void**)&gxT,   g_xT);
    cudaGetSymbolAddress((void**)&gws,   g_wscale);
    cudaGetSymbolAddress((void**)&gbias, g_bias);

    // 1) rotated bias
    rot_bias_kernel<<<DOUT / 256, 256>>>(d_R, d_b, gbias);

    // 2) GEMM1: W'[o][i] = S[i] * sum_k R[k][o] * weight[k][i]
    {
        dim3 grid(DIN / 128, DOUT / 128);
        sgemm_tn<<<grid, 256>>>(d_R, DOUT, d_w, DIN, gW, DIN, KR, d_S, nullptr);
    }

    // 3) per-row quant scale
    wrowmax_kernel<<<DOUT, 256>>>(gW, gws);

    // 4) fused 8-bit fake-quant + transpose -> WT [i][o]
    {
        dim3 grid(DIN / 32, DOUT / 32);
        quant_transpose_kernel<<<grid, dim3(32, 8)>>>(gW, gws, gWT);
    }

    // 5) transpose x -> xT [i][s]
    {
        dim3 grid(DIN / 32, SEQ / 32);
        transpose_kernel<<<grid, dim3(32, 8)>>>(d_x, gxT, SEQ, DIN);
    }

    // 6) GEMM2: out[s][o] = sum_i xT[i][s] * WT[i][o] + b'[o]
    {
        dim3 grid(DOUT / 128, SEQ / 128);
        sgemm_tn<<<grid, 256>>>(gxT, SEQ, gWT, DOUT, d_outp, DOUT, DIN, nullptr, gbias);
    }

    // 7) 16-bit per-token fake-quant in place
    out_quant_kernel<<<SEQ, 256>>>(d_outp);
}

// round 5
// speedup vs baseline: 2.7967x; 2.7967x over previous
#include <cuda_runtime.h>
#include <cuda_fp16.h>
#include <math.h>
#include <stdint.h>

// Problem dimensions (fixed)
#define SEQ   2048
#define DIN   11008
#define DOUT  4096
#define KR    4096

// ---------------------------------------------------------------------------
// Scratch (__device__ globals; no cudaMalloc allowed)
// ---------------------------------------------------------------------------
__device__ float  g_W [(size_t)DOUT * DIN];   // W' fp32 [o][i]
__device__ __half g_Q [(size_t)DOUT * DIN];   // quantized ints as fp16 [o][i]
__device__ __half g_A0[(size_t)DOUT * KR];    // (R^T * 64) hi  [o][k]
__device__ __half g_A1[(size_t)DOUT * KR];    // lo
__device__ __half g_B0[(size_t)DIN  * KR];    // ((w*S)^T * 64) hi [i][k]
__device__ __half g_B1[(size_t)DIN  * KR];    // lo
__device__ __half g_X0[(size_t)SEQ  * DIN];   // x hi [s][i]
__device__ __half g_X1[(size_t)SEQ  * DIN];   // x lo
__device__ float  g_wscale[DOUT];
__device__ float  g_bias  [DOUT];

// ---------------------------------------------------------------------------
// PTX helpers (sm_100 base target: cp.async + ldmatrix + mma.sync)
// ---------------------------------------------------------------------------
__device__ __forceinline__ uint32_t smem_u32(const void* p) {
    return (uint32_t)__cvta_generic_to_shared(p);
}
__device__ __forceinline__ void cp16(uint32_t s, const void* g) {
    asm volatile("cp.async.cg.shared.global [%0], [%1], 16;\n" :: "r"(s), "l"(g));
}
__device__ __forceinline__ void cp_commit() {
    asm volatile("cp.async.commit_group;" ::: "memory");
}
template<int N>
__device__ __forceinline__ void cp_wait() {
    asm volatile("cp.async.wait_group %0;" :: "n"(N) : "memory");
}
__device__ __forceinline__ void ldm4(uint32_t* r, uint32_t addr) {
    asm volatile("ldmatrix.sync.aligned.m8n8.x4.shared.b16 {%0,%1,%2,%3}, [%4];"
        : "=r"(r[0]), "=r"(r[1]), "=r"(r[2]), "=r"(r[3]) : "r"(addr));
}
__device__ __forceinline__ void mma16816(float* d, const uint32_t* a, uint32_t b0, uint32_t b1) {
    asm volatile("mma.sync.aligned.m16n8k16.row.col.f32.f16.f16.f32 "
        "{%0,%1,%2,%3}, {%4,%5,%6,%7}, {%8,%9}, {%0,%1,%2,%3};"
        : "+f"(d[0]), "+f"(d[1]), "+f"(d[2]), "+f"(d[3])
        : "r"(a[0]), "r"(a[1]), "r"(a[2]), "r"(a[3]), "r"(b0), "r"(b1));
}

// ---------------------------------------------------------------------------
// Multistage fp16 GEMM: C[M][N] = alpha * sum_t A_t[M][K] @ B_t[N][K]^T (+epi)
// Tile 128x128x32, 256 threads (2x4 warps of 64x32), 4-stage cp.async.
// Smem swizzle: 16B chunk c at row r stored at c ^ ((r>>1)&3).
// ---------------------------------------------------------------------------
struct TermsH { const __half* A[3]; const __half* B[3]; };

#define STAGES   4
#define SM_STAGE 16384
#define SMEM_DYN (STAGES * SM_STAGE + 1024)

__global__ __launch_bounds__(256)
void gemm_mma(TermsH t, int nT, int K, float* __restrict__ C, int ldc, float alpha,
              const float* __restrict__ cs, const float* __restrict__ cb)
{
    extern __shared__ char raw[];
    const uint32_t base = (smem_u32(raw) + 1023u) & ~1023u;

    const int tid  = threadIdx.x;
    const int lane = tid & 31, wid = tid >> 5;
    const int wr   = wid & 1, wc = wid >> 1;          // 2 x 4 warp grid
    const int m0   = blockIdx.y * 128, n0 = blockIdx.x * 128;

    // loader: 512 chunks (128 rows x 4 x 16B) per matrix, 2 per thread each
    uint32_t so[2]; uint32_t go[2];
    #pragma unroll
    for (int j = 0; j < 2; j++) {
        int ch = tid + j * 256;
        int r = ch >> 2, c = ch & 3;
        so[j] = (uint32_t)(r * 64 + ((c ^ ((r >> 1) & 3)) << 4));
        go[j] = (uint32_t)(r * K + c * 8);            // halves
    }

    // ldmatrix per-lane byte offsets
    uint32_t aoff[2][4], boff[2][2];
    #pragma unroll
    for (int ks = 0; ks < 2; ks++) {
        #pragma unroll
        for (int mf = 0; mf < 4; mf++) {
            int r = wr * 64 + mf * 16 + (lane & 15);
            int c = ks * 2 + (lane >> 4);
            aoff[ks][mf] = (uint32_t)(r * 64 + ((c ^ ((r >> 1) & 3)) << 4));
        }
        #pragma unroll
        for (int nf = 0; nf < 2; nf++) {
            int r = wc * 32 + nf * 16 + (lane & 7) + ((lane >> 4) << 3);
            int c = ks * 2 + ((lane >> 3) & 1);
            boff[ks][nf] = (uint32_t)(r * 64 + ((c ^ ((r >> 1) & 3)) << 4));
        }
    }

    const int kpt   = K >> 5;
    const int total = nT * kpt;
    int lt = 0, lk = 0;
    auto issue = [&](int stage) {
        const __half* ga = t.A[lt] + (size_t)m0 * K + lk * 32;
        const __half* gb = t.B[lt] + (size_t)n0 * K + lk * 32;
        const uint32_t sa = base + stage * SM_STAGE;
        const uint32_t sb = sa + 8192;
        #pragma unroll
        for (int j = 0; j < 2; j++) {
            cp16(sa + so[j], ga + go[j]);
            cp16(sb + so[j], gb + go[j]);
        }
        if (++lk == kpt) { lk = 0; ++lt; }
    };

    float acc[4][4][4];
    #pragma unroll
    for (int i = 0; i < 4; i++)
        #pragma unroll
        for (int j = 0; j < 4; j++)
            #pragma unroll
            for (int k = 0; k < 4; k++) acc[i][j][k] = 0.0f;

    #pragma unroll
    for (int s = 0; s < STAGES - 1; s++) {
        if (s < total) issue(s);
        cp_commit();
    }

    for (int i = 0; i < total; i++) {
        cp_wait<STAGES - 2>();
        __syncthreads();

        const int ns = i + STAGES - 1;
        if (ns < total) issue(ns & 3);
        cp_commit();

        const uint32_t sa = base + (i & 3) * SM_STAGE;
        const uint32_t sb = sa + 8192;

        uint32_t af[2][4][4], bf[2][2][4];
        #pragma unroll
        for (int ks = 0; ks < 2; ks++) {
            #pragma unroll
            for (int mf = 0; mf < 4; mf++) ldm4(af[ks][mf], sa + aoff[ks][mf]);
            #pragma unroll
            for (int np = 0; np < 2; np++) ldm4(bf[ks][np], sb + boff[ks][np]);
        }
        #pragma unroll
        for (int ks = 0; ks < 2; ks++)
            #pragma unroll
            for (int mf = 0; mf < 4; mf++)
                #pragma unroll
                for (int np = 0; np < 2; np++) {
                    mma16816(acc[mf][np * 2],     af[ks][mf], bf[ks][np][0], bf[ks][np][1]);
                    mma16816(acc[mf][np * 2 + 1], af[ks][mf], bf[ks][np][2], bf[ks][np][3]);
                }
    }

    // epilogue: d0,d1 -> (row, 2q..2q+1); d2,d3 -> (row+8, ...)
    const int ln4 = lane >> 2, lq = lane & 3;
    #pragma unroll
    for (int mf = 0; mf < 4; mf++) {
        #pragma unroll
        for (int h = 0; h < 2; h++) {
            const int row = m0 + wr * 64 + mf * 16 + ln4 + h * 8;
            float* crow = C + (size_t)row * ldc;
            #pragma unroll
            for (int nf = 0; nf < 4; nf++) {
                const int col = n0 + wc * 32 + nf * 8 + lq * 2;
                float v0 = acc[mf][nf][h * 2]     * alpha;
                float v1 = acc[mf][nf][h * 2 + 1] * alpha;
                if (cs) {
                    v0 = v0 * __ldg(&cs[col])     + __ldg(&cb[col]);
                    v1 = v1 * __ldg(&cs[col + 1]) + __ldg(&cb[col + 1]);
                }
                *(float2*)&crow[col] = make_float2(v0, v1);
            }
        }
    }
}

// ---------------------------------------------------------------------------
// Prep: transpose + pre-scale + 2-way fp16 split.
// out[c][r] = split(src[r][c] * mul * (colScale ? colScale[c] : 1))
// ---------------------------------------------------------------------------
__global__ void tsplit2h(const float* __restrict__ src, int rows, int cols,
                         const float* __restrict__ colScale, float mul,
                         __half* __restrict__ o0, __half* __restrict__ o1)
{
    __shared__ float tsh[32][33];
    const int c0 = blockIdx.x * 32, r0 = blockIdx.y * 32;
    #pragma unroll
    for (int rr = threadIdx.y; rr < 32; rr += 8)
        tsh[rr][threadIdx.x] = src[(size_t)(r0 + rr) * cols + c0 + threadIdx.x];
    __syncthreads();
    #pragma unroll
    for (int cc = threadIdx.y; cc < 32; cc += 8) {
        const int c = c0 + cc;
        float v = tsh[threadIdx.x][cc] * mul;
        if (colScale) v *= colScale[c];
        __half hi = __float2half_rn(v);
        __half lo = __float2half_rn(v - __half2float(hi));
        const size_t off = (size_t)c * rows + r0 + threadIdx.x;
        o0[off] = hi; o1[off] = lo;
    }
}

// ---------------------------------------------------------------------------
// x -> 2-way fp16 split (elementwise, vectorized)
// ---------------------------------------------------------------------------
__device__ __forceinline__ uint32_t packh(__half a, __half b) {
    uint16_t ua = *(uint16_t*)&a, ub = *(uint16_t*)&b;
    return (uint32_t)ua | ((uint32_t)ub << 16);
}
__global__ void split2h(const float* __restrict__ x,
                        __half* __restrict__ o0, __half* __restrict__ o1)
{
    const size_t i = (size_t)blockIdx.x * blockDim.x + threadIdx.x;
    float4 v = ((const float4*)x)[i];
    __half hx = __float2half_rn(v.x), hy = __float2half_rn(v.y);
    __half hz = __float2half_rn(v.z), hw = __float2half_rn(v.w);
    __half lx = __float2half_rn(v.x - __half2float(hx));
    __half ly = __float2half_rn(v.y - __half2float(hy));
    __half lz = __float2half_rn(v.z - __half2float(hz));
    __half lw = __float2half_rn(v.w - __half2float(hw));
    ((uint2*)o0)[i] = make_uint2(packh(hx, hy), packh(hz, hw));
    ((uint2*)o1)[i] = make_uint2(packh(lx, ly), packh(lz, lw));
}

// ---------------------------------------------------------------------------
// Rotated bias: b'[o] = sum_k R[k][o] * bias[k]
// ---------------------------------------------------------------------------
__global__ void rot_bias_kernel(const float* __restrict__ R,
                                const float* __restrict__ bias,
                                float* __restrict__ out)
{
    const int o = blockIdx.x * blockDim.x + threadIdx.x;
    if (o >= DOUT) return;
    float acc = 0.0f;
    for (int k = 0; k < KR; k++)
        acc = fmaf(R[(size_t)k * DOUT + o], bias[k], acc);
    out[o] = acc;
}

// ---------------------------------------------------------------------------
// Per-row max(|W'|) -> quant scale
// ---------------------------------------------------------------------------
__device__ __forceinline__ float block_reduce_max(float v) {
    __shared__ float sh[32];
    int lane = threadIdx.x & 31;
    int wid  = threadIdx.x >> 5;
    #pragma unroll
    for (int o = 16; o; o >>= 1) v = fmaxf(v, __shfl_xor_sync(0xffffffffu, v, o));
    if (lane == 0) sh[wid] = v;
    __syncthreads();
    int nw = blockDim.x >> 5;
    v = (threadIdx.x < (unsigned)nw) ? sh[threadIdx.x] : 0.0f;
    if (wid == 0) {
        #pragma unroll
        for (int o = 16; o; o >>= 1) v = fmaxf(v, __shfl_xor_sync(0xffffffffu, v, o));
    }
    if (threadIdx.x == 0) sh[0] = v;
    __syncthreads();
    return sh[0];
}
__global__ void wrowmax_kernel(const float* __restrict__ W, float* __restrict__ scale)
{
    const int row = blockIdx.x;
    const float* p = W + (size_t)row * DIN;
    float m = 0.0f;
    for (int i = threadIdx.x * 4; i < DIN; i += blockDim.x * 4) {
        float4 v = *(const float4*)&p[i];
        m = fmaxf(m, fmaxf(fmaxf(fabsf(v.x), fabsf(v.y)), fmaxf(fabsf(v.z), fabsf(v.w))));
    }
    m = block_reduce_max(m);
    if (threadIdx.x == 0)
        scale[row] = fmaxf(__fdiv_rn(m, 127.0f), 1e-8f);
}

// ---------------------------------------------------------------------------
// 8-bit fake-quant to fp16 integers (exact): q = clamp(rint(W/s_o))
// ---------------------------------------------------------------------------
__global__ void quant_h_kernel(const float* __restrict__ W,
                               const float* __restrict__ scale,
                               __half* __restrict__ q)
{
    const size_t idx4 = (size_t)blockIdx.x * blockDim.x + threadIdx.x;
    const int row = (int)(idx4 / (DIN / 4));
    const float s = scale[row];
    float4 v = ((const float4*)W)[idx4];
    float qx = fminf(fmaxf(rintf(__fdiv_rn(v.x, s)), -128.0f), 127.0f);
    float qy = fminf(fmaxf(rintf(__fdiv_rn(v.y, s)), -128.0f), 127.0f);
    float qz = fminf(fmaxf(rintf(__fdiv_rn(v.z, s)), -128.0f), 127.0f);
    float qw = fminf(fmaxf(rintf(__fdiv_rn(v.w, s)), -128.0f), 127.0f);
    ((uint2*)q)[idx4] = make_uint2(
        packh(__float2half_rn(qx), __float2half_rn(qy)),
        packh(__float2half_rn(qz), __float2half_rn(qw)));
}

// ---------------------------------------------------------------------------
// 16-bit per-token fake-quant, in place
// ---------------------------------------------------------------------------
__global__ void out_quant_kernel(float* __restrict__ out)
{
    const int s = blockIdx.x;
    float* p = out + (size_t)s * DOUT;
    float m = 0.0f;
    for (int i = threadIdx.x * 4; i < DOUT; i += blockDim.x * 4) {
        float4 v = *(const float4*)&p[i];
        m = fmaxf(m, fmaxf(fmaxf(fabsf(v.x), fabsf(v.y)), fmaxf(fabsf(v.z), fabsf(v.w))));
    }
    m = block_reduce_max(m);
    const float sc = fmaxf(__fdiv_rn(m, 32767.0f), 1e-8f);
    for (int i = threadIdx.x * 4; i < DOUT; i += blockDim.x * 4) {
        float4 v = *(const float4*)&p[i];
        v.x = fminf(fmaxf(rintf(__fdiv_rn(v.x, sc)), -32768.0f), 32767.0f) * sc;
        v.y = fminf(fmaxf(rintf(__fdiv_rn(v.y, sc)), -32768.0f), 32767.0f) * sc;
        v.z = fminf(fmaxf(rintf(__fdiv_rn(v.z, sc)), -32768.0f), 32767.0f) * sc;
        v.w = fminf(fmaxf(rintf(__fdiv_rn(v.w, sc)), -32768.0f), 32767.0f) * sc;
        *(float4*)&p[i] = v;
    }
}

// ---------------------------------------------------------------------------
// Launch
// ---------------------------------------------------------------------------
extern "C" void kernel_launch(void* const* d_in, const int* in_sizes, int n_in,
                              void* d_out, int out_size)
{
    const float* d_x = (const float*)d_in[0];
    const float* d_w = (const float*)d_in[1];
    const float* d_b = (const float*)d_in[2];
    const float* d_S = (const float*)d_in[3];
    const float* d_R = (const float*)d_in[4];
    float*       d_o = (float*)d_out;

    float *gW, *gws, *gbias;
    __half *gQ, *gA0, *gA1, *gB0, *gB1, *gX0, *gX1;
    cudaGetSymbolAddress((void**)&gW,   g_W);
    cudaGetSymbolAddress((void**)&gQ,   g_Q);
    cudaGetSymbolAddress((void**)&gA0,  g_A0);
    cudaGetSymbolAddress((void**)&gA1,  g_A1);
    cudaGetSymbolAddress((void**)&gB0,  g_B0);
    cudaGetSymbolAddress((void**)&gB1,  g_B1);
    cudaGetSymbolAddress((void**)&gX0,  g_X0);
    cudaGetSymbolAddress((void**)&gX1,  g_X1);
    cudaGetSymbolAddress((void**)&gws,  g_wscale);
    cudaGetSymbolAddress((void**)&gbias, g_bias);

    cudaFuncSetAttribute(gemm_mma, cudaFuncAttributeMaxDynamicSharedMemorySize, SMEM_DYN);

    // 1) rotated bias
    rot_bias_kernel<<<DOUT / 256, 256>>>(d_R, d_b, gbias);

    // 2) prep splits (pre-scaled by 2^6 each so lo stays in fp16 normal range)
    tsplit2h<<<dim3(DOUT / 32, KR / 32), dim3(32, 8)>>>(d_R, KR, DOUT, nullptr, 64.0f, gA0, gA1);
    tsplit2h<<<dim3(DIN / 32, KR / 32),  dim3(32, 8)>>>(d_w, KR, DIN,  d_S,    64.0f, gB0, gB1);
    split2h<<<(int)((size_t)SEQ * DIN / 4 / 256), 256>>>(d_x, gX0, gX1);

    // 3) GEMM1: W' = R^T (weight*S), 3-term fp16 split, alpha = 2^-12 un-scale
    {
        TermsH t;
        t.A[0] = gA0; t.B[0] = gB0;
        t.A[1] = gA0; t.B[1] = gB1;
        t.A[2] = gA1; t.B[2] = gB0;
        dim3 grid(DIN / 128, DOUT / 128);
        gemm_mma<<<grid, 256, SMEM_DYN>>>(t, 3, KR, gW, DIN, 1.0f / 4096.0f, nullptr, nullptr);
    }

    // 4) weight quant scale + quantize to fp16 ints
    wrowmax_kernel<<<DOUT, 256>>>(gW, gws);
    quant_h_kernel<<<(int)((size_t)DOUT * DIN / 4 / 256), 256>>>(gW, gws, gQ);

    // 5) GEMM2: out = (x @ q^T) * s_o + b'_o, 2-term x split (q exact in fp16)
    {
        TermsH t;
        t.A[0] = gX0; t.B[0] = gQ;
        t.A[1] = gX1; t.B[1] = gQ;
        t.A[2] = nullptr; t.B[2] = nullptr;
        dim3 grid(DOUT / 128, SEQ / 128);
        gemm_mma<<<grid, 256, SMEM_DYN>>>(t, 2, DIN, d_o, DOUT, 1.0f, gws, gbias);
    }

    // 6) 16-bit per-token fake-quant in place
    out_quant_kernel<<<SEQ, 256>>>(d_o);
}

// round 6
// speedup vs baseline: 2.7997x; 1.0011x over previous
#include <cuda_runtime.h>
#include <cuda_fp16.h>
#include <math.h>
#include <stdint.h>

// Problem dimensions (fixed)
#define SEQ   2048
#define DIN   11008
#define DOUT  4096
#define KR    4096

// ---------------------------------------------------------------------------
// Scratch (__device__ globals; no cudaMalloc allowed)
// ---------------------------------------------------------------------------
__device__ float  g_W [(size_t)DOUT * DIN];   // W' fp32 [o][i]
__device__ __half g_Q [(size_t)DOUT * DIN];   // quantized ints as fp16 [o][i]
__device__ __half g_A0[(size_t)DOUT * KR];    // (R^T * 64) hi  [o][k]
__device__ __half g_A1[(size_t)DOUT * KR];    // lo
__device__ __half g_B0[(size_t)DIN  * KR];    // ((w*S)^T * 64) hi [i][k]
__device__ __half g_B1[(size_t)DIN  * KR];    // lo
__device__ __half g_X0[(size_t)SEQ  * DIN];   // x hi [s][i]
__device__ __half g_X1[(size_t)SEQ  * DIN];   // x lo
__device__ float  g_wscale[DOUT];
__device__ float  g_bias  [DOUT];

// ---------------------------------------------------------------------------
// PTX helpers (sm_100 base target: cp.async + ldmatrix + mma.sync)
// ---------------------------------------------------------------------------
__device__ __forceinline__ uint32_t smem_u32(const void* p) {
    return (uint32_t)__cvta_generic_to_shared(p);
}
__device__ __forceinline__ void cp16(uint32_t s, const void* g) {
    asm volatile("cp.async.cg.shared.global [%0], [%1], 16;\n" :: "r"(s), "l"(g));
}
__device__ __forceinline__ void cp_commit() {
    asm volatile("cp.async.commit_group;" ::: "memory");
}
template<int N>
__device__ __forceinline__ void cp_wait() {
    asm volatile("cp.async.wait_group %0;" :: "n"(N) : "memory");
}
__device__ __forceinline__ void ldm4(uint32_t* r, uint32_t addr) {
    asm volatile("ldmatrix.sync.aligned.m8n8.x4.shared.b16 {%0,%1,%2,%3}, [%4];"
        : "=r"(r[0]), "=r"(r[1]), "=r"(r[2]), "=r"(r[3]) : "r"(addr));
}
__device__ __forceinline__ void mma16816(float* d, const uint32_t* a, uint32_t b0, uint32_t b1) {
    asm volatile("mma.sync.aligned.m16n8k16.row.col.f32.f16.f16.f32 "
        "{%0,%1,%2,%3}, {%4,%5,%6,%7}, {%8,%9}, {%0,%1,%2,%3};"
        : "+f"(d[0]), "+f"(d[1]), "+f"(d[2]), "+f"(d[3])
        : "r"(a[0]), "r"(a[1]), "r"(a[2]), "r"(a[3]), "r"(b0), "r"(b1));
}

// ---------------------------------------------------------------------------
// Multistage fp16 GEMM: C[M][N] = alpha * sum_t A_t[M][K] @ B_t[N][K]^T (+epi)
// Tile 128x128x32, 256 threads (2x4 warps of 64x32), 4-stage cp.async.
// Smem swizzle: 16B chunk c at row r stored at c ^ ((r>>1)&3).
// Rasterization: blockIdx.x = M-tile (fast-varying) so a wave shares B-tiles
// in L2 (B is the large operand in both GEMMs); blockIdx.y = N-tile.
// ---------------------------------------------------------------------------
struct TermsH { const __half* A[3]; const __half* B[3]; };

#define STAGES   4
#define SM_STAGE 16384
#define SMEM_DYN (STAGES * SM_STAGE + 1024)

__global__ __launch_bounds__(256)
void gemm_mma(TermsH t, int nT, int K, float* __restrict__ C, int ldc, float alpha,
              const float* __restrict__ cs, const float* __restrict__ cb)
{
    extern __shared__ char raw[];
    const uint32_t base = (smem_u32(raw) + 1023u) & ~1023u;

    const int tid  = threadIdx.x;
    const int lane = tid & 31, wid = tid >> 5;
    const int wr   = wid & 1, wc = wid >> 1;          // 2 x 4 warp grid
    const int m0   = blockIdx.x * 128, n0 = blockIdx.y * 128;   // M fast-varying

    // loader: 512 chunks (128 rows x 4 x 16B) per matrix, 2 per thread each
    uint32_t so[2]; uint32_t go[2];
    #pragma unroll
    for (int j = 0; j < 2; j++) {
        int ch = tid + j * 256;
        int r = ch >> 2, c = ch & 3;
        so[j] = (uint32_t)(r * 64 + ((c ^ ((r >> 1) & 3)) << 4));
        go[j] = (uint32_t)(r * K + c * 8);            // halves
    }

    // ldmatrix per-lane byte offsets
    uint32_t aoff[2][4], boff[2][2];
    #pragma unroll
    for (int ks = 0; ks < 2; ks++) {
        #pragma unroll
        for (int mf = 0; mf < 4; mf++) {
            int r = wr * 64 + mf * 16 + (lane & 15);
            int c = ks * 2 + (lane >> 4);
            aoff[ks][mf] = (uint32_t)(r * 64 + ((c ^ ((r >> 1) & 3)) << 4));
        }
        #pragma unroll
        for (int nf = 0; nf < 2; nf++) {
            int r = wc * 32 + nf * 16 + (lane & 7) + ((lane >> 4) << 3);
            int c = ks * 2 + ((lane >> 3) & 1);
            boff[ks][nf] = (uint32_t)(r * 64 + ((c ^ ((r >> 1) & 3)) << 4));
        }
    }

    const int kpt   = K >> 5;
    const int total = nT * kpt;
    int lt = 0, lk = 0;
    auto issue = [&](int stage) {
        const __half* ga = t.A[lt] + (size_t)m0 * K + lk * 32;
        const __half* gb = t.B[lt] + (size_t)n0 * K + lk * 32;
        const uint32_t sa = base + stage * SM_STAGE;
        const uint32_t sb = sa + 8192;
        #pragma unroll
        for (int j = 0; j < 2; j++) {
            cp16(sa + so[j], ga + go[j]);
            cp16(sb + so[j], gb + go[j]);
        }
        if (++lk == kpt) { lk = 0; ++lt; }
    };

    float acc[4][4][4];
    #pragma unroll
    for (int i = 0; i < 4; i++)
        #pragma unroll
        for (int j = 0; j < 4; j++)
            #pragma unroll
            for (int k = 0; k < 4; k++) acc[i][j][k] = 0.0f;

    #pragma unroll
    for (int s = 0; s < STAGES - 1; s++) {
        if (s < total) issue(s);
        cp_commit();
    }

    for (int i = 0; i < total; i++) {
        cp_wait<STAGES - 2>();
        __syncthreads();

        const int ns = i + STAGES - 1;
        if (ns < total) issue(ns & 3);
        cp_commit();

        const uint32_t sa = base + (i & 3) * SM_STAGE;
        const uint32_t sb = sa + 8192;

        uint32_t af[2][4][4], bf[2][2][4];
        #pragma unroll
        for (int ks = 0; ks < 2; ks++) {
            #pragma unroll
            for (int mf = 0; mf < 4; mf++) ldm4(af[ks][mf], sa + aoff[ks][mf]);
            #pragma unroll
            for (int np = 0; np < 2; np++) ldm4(bf[ks][np], sb + boff[ks][np]);
        }
        #pragma unroll
        for (int ks = 0; ks < 2; ks++)
            #pragma unroll
            for (int mf = 0; mf < 4; mf++)
                #pragma unroll
                for (int np = 0; np < 2; np++) {
                    mma16816(acc[mf][np * 2],     af[ks][mf], bf[ks][np][0], bf[ks][np][1]);
                    mma16816(acc[mf][np * 2 + 1], af[ks][mf], bf[ks][np][2], bf[ks][np][3]);
                }
    }

    // epilogue: d0,d1 -> (row, 2q..2q+1); d2,d3 -> (row+8, ...)
    const int ln4 = lane >> 2, lq = lane & 3;
    #pragma unroll
    for (int mf = 0; mf < 4; mf++) {
        #pragma unroll
        for (int h = 0; h < 2; h++) {
            const int row = m0 + wr * 64 + mf * 16 + ln4 + h * 8;
            float* crow = C + (size_t)row * ldc;
            #pragma unroll
            for (int nf = 0; nf < 4; nf++) {
                const int col = n0 + wc * 32 + nf * 8 + lq * 2;
                float v0 = acc[mf][nf][h * 2]     * alpha;
                float v1 = acc[mf][nf][h * 2 + 1] * alpha;
                if (cs) {
                    v0 = v0 * __ldg(&cs[col])     + __ldg(&cb[col]);
                    v1 = v1 * __ldg(&cs[col + 1]) + __ldg(&cb[col + 1]);
                }
                *(float2*)&crow[col] = make_float2(v0, v1);
            }
        }
    }
}

// ---------------------------------------------------------------------------
// Prep: transpose + pre-scale + 2-way fp16 split.
// out[c][r] = split(src[r][c] * mul * (colScale ? colScale[c] : 1))
// ---------------------------------------------------------------------------
__global__ void tsplit2h(const float* __restrict__ src, int rows, int cols,
                         const float* __restrict__ colScale, float mul,
                         __half* __restrict__ o0, __half* __restrict__ o1)
{
    __shared__ float tsh[32][33];
    const int c0 = blockIdx.x * 32, r0 = blockIdx.y * 32;
    #pragma unroll
    for (int rr = threadIdx.y; rr < 32; rr += 8)
        tsh[rr][threadIdx.x] = src[(size_t)(r0 + rr) * cols + c0 + threadIdx.x];
    __syncthreads();
    #pragma unroll
    for (int cc = threadIdx.y; cc < 32; cc += 8) {
        const int c = c0 + cc;
        float v = tsh[threadIdx.x][cc] * mul;
        if (colScale) v *= colScale[c];
        __half hi = __float2half_rn(v);
        __half lo = __float2half_rn(v - __half2float(hi));
        const size_t off = (size_t)c * rows + r0 + threadIdx.x;
        o0[off] = hi; o1[off] = lo;
    }
}

// ---------------------------------------------------------------------------
// x -> 2-way fp16 split (elementwise, vectorized)
// ---------------------------------------------------------------------------
__device__ __forceinline__ uint32_t packh(__half a, __half b) {
    uint16_t ua = *(uint16_t*)&a, ub = *(uint16_t*)&b;
    return (uint32_t)ua | ((uint32_t)ub << 16);
}
__global__ void split2h(const float* __restrict__ x,
                        __half* __restrict__ o0, __half* __restrict__ o1)
{
    const size_t i = (size_t)blockIdx.x * blockDim.x + threadIdx.x;
    float4 v = ((const float4*)x)[i];
    __half hx = __float2half_rn(v.x), hy = __float2half_rn(v.y);
    __half hz = __float2half_rn(v.z), hw = __float2half_rn(v.w);
    __half lx = __float2half_rn(v.x - __half2float(hx));
    __half ly = __float2half_rn(v.y - __half2float(hy));
    __half lz = __float2half_rn(v.z - __half2float(hz));
    __half lw = __float2half_rn(v.w - __half2float(hw));
    ((uint2*)o0)[i] = make_uint2(packh(hx, hy), packh(hz, hw));
    ((uint2*)o1)[i] = make_uint2(packh(lx, ly), packh(lz, lw));
}

// ---------------------------------------------------------------------------
// Rotated bias: b'[o] = sum_k R[k][o] * bias[k]
// ---------------------------------------------------------------------------
__global__ void rot_bias_kernel(const float* __restrict__ R,
                                const float* __restrict__ bias,
                                float* __restrict__ out)
{
    const int o = blockIdx.x * blockDim.x + threadIdx.x;
    if (o >= DOUT) return;
    float acc = 0.0f;
    for (int k = 0; k < KR; k++)
        acc = fmaf(R[(size_t)k * DOUT + o], bias[k], acc);
    out[o] = acc;
}

// ---------------------------------------------------------------------------
// Per-row max(|W'|) -> quant scale
// ---------------------------------------------------------------------------
__device__ __forceinline__ float block_reduce_max(float v) {
    __shared__ float sh[32];
    int lane = threadIdx.x & 31;
    int wid  = threadIdx.x >> 5;
    #pragma unroll
    for (int o = 16; o; o >>= 1) v = fmaxf(v, __shfl_xor_sync(0xffffffffu, v, o));
    if (lane == 0) sh[wid] = v;
    __syncthreads();
    int nw = blockDim.x >> 5;
    v = (threadIdx.x < (unsigned)nw) ? sh[threadIdx.x] : 0.0f;
    if (wid == 0) {
        #pragma unroll
        for (int o = 16; o; o >>= 1) v = fmaxf(v, __shfl_xor_sync(0xffffffffu, v, o));
    }
    if (threadIdx.x == 0) sh[0] = v;
    __syncthreads();
    return sh[0];
}
__global__ void wrowmax_kernel(const float* __restrict__ W, float* __restrict__ scale)
{
    const int row = blockIdx.x;
    const float* p = W + (size_t)row * DIN;
    float m = 0.0f;
    for (int i = threadIdx.x * 4; i < DIN; i += blockDim.x * 4) {
        float4 v = *(const float4*)&p[i];
        m = fmaxf(m, fmaxf(fmaxf(fabsf(v.x), fabsf(v.y)), fmaxf(fabsf(v.z), fabsf(v.w))));
    }
    m = block_reduce_max(m);
    if (threadIdx.x == 0)
        scale[row] = fmaxf(__fdiv_rn(m, 127.0f), 1e-8f);
}

// ---------------------------------------------------------------------------
// 8-bit fake-quant to fp16 integers (exact): q = clamp(rint(W/s_o))
// ---------------------------------------------------------------------------
__global__ void quant_h_kernel(const float* __restrict__ W,
                               const float* __restrict__ scale,
                               __half* __restrict__ q)
{
    const size_t idx4 = (size_t)blockIdx.x * blockDim.x + threadIdx.x;
    const int row = (int)(idx4 / (DIN / 4));
    const float s = scale[row];
    float4 v = ((const float4*)W)[idx4];
    float qx = fminf(fmaxf(rintf(__fdiv_rn(v.x, s)), -128.0f), 127.0f);
    float qy = fminf(fmaxf(rintf(__fdiv_rn(v.y, s)), -128.0f), 127.0f);
    float qz = fminf(fmaxf(rintf(__fdiv_rn(v.z, s)), -128.0f), 127.0f);
    float qw = fminf(fmaxf(rintf(__fdiv_rn(v.w, s)), -128.0f), 127.0f);
    ((uint2*)q)[idx4] = make_uint2(
        packh(__float2half_rn(qx), __float2half_rn(qy)),
        packh(__float2half_rn(qz), __float2half_rn(qw)));
}

// ---------------------------------------------------------------------------
// 16-bit per-token fake-quant, in place
// ---------------------------------------------------------------------------
__global__ void out_quant_kernel(float* __restrict__ out)
{
    const int s = blockIdx.x;
    float* p = out + (size_t)s * DOUT;
    float m = 0.0f;
    for (int i = threadIdx.x * 4; i < DOUT; i += blockDim.x * 4) {
        float4 v = *(const float4*)&p[i];
        m = fmaxf(m, fmaxf(fmaxf(fabsf(v.x), fabsf(v.y)), fmaxf(fabsf(v.z), fabsf(v.w))));
    }
    m = block_reduce_max(m);
    const float sc = fmaxf(__fdiv_rn(m, 32767.0f), 1e-8f);
    for (int i = threadIdx.x * 4; i < DOUT; i += blockDim.x * 4) {
        float4 v = *(const float4*)&p[i];
        v.x = fminf(fmaxf(rintf(__fdiv_rn(v.x, sc)), -32768.0f), 32767.0f) * sc;
        v.y = fminf(fmaxf(rintf(__fdiv_rn(v.y, sc)), -32768.0f), 32767.0f) * sc;
        v.z = fminf(fmaxf(rintf(__fdiv_rn(v.z, sc)), -32768.0f), 32767.0f) * sc;
        v.w = fminf(fmaxf(rintf(__fdiv_rn(v.w, sc)), -32768.0f), 32767.0f) * sc;
        *(float4*)&p[i] = v;
    }
}

// ---------------------------------------------------------------------------
// Launch
// ---------------------------------------------------------------------------
extern "C" void kernel_launch(void* const* d_in, const int* in_sizes, int n_in,
                              void* d_out, int out_size)
{
    const float* d_x = (const float*)d_in[0];
    const float* d_w = (const float*)d_in[1];
    const float* d_b = (const float*)d_in[2];
    const float* d_S = (const float*)d_in[3];
    const float* d_R = (const float*)d_in[4];
    float*       d_o = (float*)d_out;

    float *gW, *gws, *gbias;
    __half *gQ, *gA0, *gA1, *gB0, *gB1, *gX0, *gX1;
    cudaGetSymbolAddress((void**)&gW,   g_W);
    cudaGetSymbolAddress((void**)&gQ,   g_Q);
    cudaGetSymbolAddress((void**)&gA0,  g_A0);
    cudaGetSymbolAddress((void**)&gA1,  g_A1);
    cudaGetSymbolAddress((void**)&gB0,  g_B0);
    cudaGetSymbolAddress((void**)&gB1,  g_B1);
    cudaGetSymbolAddress((void**)&gX0,  g_X0);
    cudaGetSymbolAddress((void**)&gX1,  g_X1);
    cudaGetSymbolAddress((void**)&gws,  g_wscale);
    cudaGetSymbolAddress((void**)&gbias, g_bias);

    cudaFuncSetAttribute(gemm_mma, cudaFuncAttributeMaxDynamicSharedMemorySize, SMEM_DYN);

    // 1) rotated bias
    rot_bias_kernel<<<DOUT / 256, 256>>>(d_R, d_b, gbias);

    // 2) prep splits (pre-scaled by 2^6 each so lo stays in fp16 normal range)
    tsplit2h<<<dim3(DOUT / 32, KR / 32), dim3(32, 8)>>>(d_R, KR, DOUT, nullptr, 64.0f, gA0, gA1);
    tsplit2h<<<dim3(DIN / 32, KR / 32),  dim3(32, 8)>>>(d_w, KR, DIN,  d_S,    64.0f, gB0, gB1);
    split2h<<<(int)((size_t)SEQ * DIN / 4 / 256), 256>>>(d_x, gX0, gX1);

    // 3) GEMM1: W' = R^T (weight*S), 3-term fp16 split, alpha = 2^-12 un-scale
    //    grid.x = M tiles (fast) so the big B operand is wave-shared in L2
    {
        TermsH t;
        t.A[0] = gA0; t.B[0] = gB0;
        t.A[1] = gA0; t.B[1] = gB1;
        t.A[2] = gA1; t.B[2] = gB0;
        dim3 grid(DOUT / 128, DIN / 128);
        gemm_mma<<<grid, 256, SMEM_DYN>>>(t, 3, KR, gW, DIN, 1.0f / 4096.0f, nullptr, nullptr);
    }

    // 4) weight quant scale + quantize to fp16 ints
    wrowmax_kernel<<<DOUT, 256>>>(gW, gws);
    quant_h_kernel<<<(int)((size_t)DOUT * DIN / 4 / 256), 256>>>(gW, gws, gQ);

    // 5) GEMM2: out = (x @ q^T) * s_o + b'_o, 2-term x split (q exact in fp16)
    {
        TermsH t;
        t.A[0] = gX0; t.B[0] = gQ;
        t.A[1] = gX1; t.B[1] = gQ;
        t.A[2] = nullptr; t.B[2] = nullptr;
        dim3 grid(SEQ / 128, DOUT / 128);
        gemm_mma<<<grid, 256, SMEM_DYN>>>(t, 2, DIN, d_o, DOUT, 1.0f, gws, gbias);
    }

    // 6) 16-bit per-token fake-quant in place
    out_quant_kernel<<<SEQ, 256>>>(d_o);
}